// round 1
// baseline (speedup 1.0000x reference)
#include <cuda_runtime.h>
#include <math.h>

#define BB 8
#define SS 2048
#define DD 768
#define HH 12
#define HD 64
#define MH (BB*SS)   // 16384

// Scratch (allocation-free rule: __device__ globals)
__device__ float g_Q[BB*HH*SS*HD];
__device__ float g_K[BB*HH*SS*HD];
__device__ float g_V[BB*HH*SS*HD];
__device__ float g_ctx[(size_t)BB*SS*DD];

// ---------------------------------------------------------------------------
// QKV projection: out[b,h,s,e] = sum_d x[b,s,d] * W[h,d,e] + bias[h,e]
// 64x64 output tile (M=rows of x, N=HD=64), K tiled by 16. 256 thr, 4x4 micro.
// grid = (MH/64, HH, 3)  z: 0=Q 1=K 2=V
// ---------------------------------------------------------------------------
__global__ __launch_bounds__(256) void qkv_kernel(
    const float* __restrict__ x,
    const float* __restrict__ Wq, const float* __restrict__ bq,
    const float* __restrict__ Wk, const float* __restrict__ bk,
    const float* __restrict__ Wv, const float* __restrict__ bv)
{
    const float* W; const float* bias; float* out;
    if (blockIdx.z == 0)      { W = Wq; bias = bq; out = g_Q; }
    else if (blockIdx.z == 1) { W = Wk; bias = bk; out = g_K; }
    else                      { W = Wv; bias = bv; out = g_V; }
    const int h = blockIdx.y;
    W    += (size_t)h * DD * HD;
    bias += h * HD;
    const int m0 = blockIdx.x * 64;

    __shared__ float As[16][68];   // As[k][m] (transposed)
    __shared__ float Bs[16][64];   // Bs[k][n]

    const int tid = threadIdx.x;
    const int tx = tid & 15, ty = tid >> 4;
    float acc[4][4] = {};

    const int am = tid >> 2;            // 0..63
    const int ak = (tid & 3) * 4;       // 0,4,8,12
    const int bk_ = tid >> 4;           // 0..15
    const int bn  = (tid & 15) * 4;     // 0..60

    for (int kt = 0; kt < DD; kt += 16) {
        float4 av = *reinterpret_cast<const float4*>(&x[(size_t)(m0 + am) * DD + kt + ak]);
        As[ak+0][am] = av.x; As[ak+1][am] = av.y; As[ak+2][am] = av.z; As[ak+3][am] = av.w;
        float4 wv4 = *reinterpret_cast<const float4*>(&W[(size_t)(kt + bk_) * HD + bn]);
        *reinterpret_cast<float4*>(&Bs[bk_][bn]) = wv4;
        __syncthreads();
        #pragma unroll
        for (int kk = 0; kk < 16; kk++) {
            float a[4], b[4];
            #pragma unroll
            for (int i = 0; i < 4; i++) a[i] = As[kk][ty*4 + i];
            float4 bb = *reinterpret_cast<float4*>(&Bs[kk][tx*4]);
            b[0]=bb.x; b[1]=bb.y; b[2]=bb.z; b[3]=bb.w;
            #pragma unroll
            for (int i = 0; i < 4; i++)
                #pragma unroll
                for (int j = 0; j < 4; j++) acc[i][j] += a[i]*b[j];
        }
        __syncthreads();
    }

    float bvv[4];
    #pragma unroll
    for (int j = 0; j < 4; j++) bvv[j] = bias[tx*4 + j];
    const int bidx = m0 / SS;   // whole tile in one batch (SS % 64 == 0)
    #pragma unroll
    for (int i = 0; i < 4; i++) {
        const int m = m0 + ty*4 + i;
        const int s = m - bidx * SS;
        size_t off = (((size_t)bidx * HH + h) * SS + s) * HD + tx*4;
        float4 o;
        o.x = acc[i][0] + bvv[0]; o.y = acc[i][1] + bvv[1];
        o.z = acc[i][2] + bvv[2]; o.w = acc[i][3] + bvv[3];
        *reinterpret_cast<float4*>(&out[off]) = o;
    }
}

// ---------------------------------------------------------------------------
// Flash-style attention per (b,h). 64-query tile, 64-key tiles, online softmax.
// grid = (SS/64, BB*HH), 256 threads, dynamic smem = 4 * 64 * 68 * 4 bytes.
// ---------------------------------------------------------------------------
#define APAD 68
__global__ __launch_bounds__(256) void attn_kernel() {
    extern __shared__ float sm[];
    float* Qst = sm;                 // [64][APAD]  Qst[d][m]
    float* Kst = sm + 64*APAD;       // [64][APAD]  Kst[d][n]
    float* Pst = sm + 2*64*APAD;     // [64][APAD]  Pst[n][m]
    float* Vs  = sm + 3*64*APAD;     // [64][APAD]  Vs[n][d]

    const int bh = blockIdx.y;
    const int q0 = blockIdx.x * 64;
    const float* Qg = g_Q + (size_t)bh * SS * HD;
    const float* Kg = g_K + (size_t)bh * SS * HD;
    const float* Vg = g_V + (size_t)bh * SS * HD;

    const int tid = threadIdx.x;
    const int tx = tid & 15, ty = tid >> 4;

    // Load Q tile transposed
    #pragma unroll
    for (int r = 0; r < 4; r++) {
        int idx = tid + r*256;
        int m = idx >> 4; int dd = (idx & 15) * 4;
        float4 v = *reinterpret_cast<const float4*>(&Qg[(size_t)(q0 + m)*HD + dd]);
        Qst[(dd+0)*APAD + m] = v.x; Qst[(dd+1)*APAD + m] = v.y;
        Qst[(dd+2)*APAD + m] = v.z; Qst[(dd+3)*APAD + m] = v.w;
    }

    float o[4][4] = {};
    float mrow[4], lrow[4];
    #pragma unroll
    for (int i = 0; i < 4; i++) { mrow[i] = -1e30f; lrow[i] = 0.f; }
    const float inv_scale = 1.0f / (sqrtf((float)HD) + 1e-6f);

    for (int k0 = 0; k0 < SS; k0 += 64) {
        __syncthreads();   // protect smem reuse from previous iteration
        #pragma unroll
        for (int r = 0; r < 4; r++) {
            int idx = tid + r*256;
            int n = idx >> 4; int dd = (idx & 15) * 4;
            float4 v = *reinterpret_cast<const float4*>(&Kg[(size_t)(k0 + n)*HD + dd]);
            Kst[(dd+0)*APAD + n] = v.x; Kst[(dd+1)*APAD + n] = v.y;
            Kst[(dd+2)*APAD + n] = v.z; Kst[(dd+3)*APAD + n] = v.w;
            float4 vv = *reinterpret_cast<const float4*>(&Vg[(size_t)(k0 + n)*HD + dd]);
            *reinterpret_cast<float4*>(&Vs[n*APAD + dd]) = vv;
        }
        __syncthreads();

        // S tile = Q @ K^T
        float s[4][4] = {};
        #pragma unroll 8
        for (int d = 0; d < 64; d++) {
            float a[4], b[4];
            #pragma unroll
            for (int i = 0; i < 4; i++) a[i] = Qst[d*APAD + ty*4 + i];
            float4 bb = *reinterpret_cast<float4*>(&Kst[d*APAD + tx*4]);
            b[0]=bb.x; b[1]=bb.y; b[2]=bb.z; b[3]=bb.w;
            #pragma unroll
            for (int i = 0; i < 4; i++)
                #pragma unroll
                for (int j = 0; j < 4; j++) s[i][j] += a[i]*b[j];
        }

        // Online softmax per row (row stats replicated across the 16 tx lanes)
        #pragma unroll
        for (int i = 0; i < 4; i++) {
            float tm = s[i][0];
            #pragma unroll
            for (int j = 1; j < 4; j++) tm = fmaxf(tm, s[i][j]);
            tm *= inv_scale;
            #pragma unroll
            for (int off = 1; off < 16; off <<= 1)
                tm = fmaxf(tm, __shfl_xor_sync(0xffffffffu, tm, off, 16));
            const float mnew = fmaxf(mrow[i], tm);
            const float alpha = __expf(mrow[i] - mnew);
            float psum = 0.f;
            #pragma unroll
            for (int j = 0; j < 4; j++) {
                s[i][j] = __expf(s[i][j]*inv_scale - mnew);
                psum += s[i][j];
            }
            #pragma unroll
            for (int off = 1; off < 16; off <<= 1)
                psum += __shfl_xor_sync(0xffffffffu, psum, off, 16);
            lrow[i] = lrow[i]*alpha + psum;
            mrow[i] = mnew;
            #pragma unroll
            for (int j = 0; j < 4; j++) o[i][j] *= alpha;
        }

        // Stage P transposed for the P@V GEMM
        #pragma unroll
        for (int i = 0; i < 4; i++)
            #pragma unroll
            for (int j = 0; j < 4; j++)
                Pst[(tx*4 + j)*APAD + ty*4 + i] = s[i][j];
        __syncthreads();

        // O += P @ V
        #pragma unroll 8
        for (int n = 0; n < 64; n++) {
            float a[4], b[4];
            #pragma unroll
            for (int i = 0; i < 4; i++) a[i] = Pst[n*APAD + ty*4 + i];
            float4 bb = *reinterpret_cast<float4*>(&Vs[n*APAD + tx*4]);
            b[0]=bb.x; b[1]=bb.y; b[2]=bb.z; b[3]=bb.w;
            #pragma unroll
            for (int i = 0; i < 4; i++)
                #pragma unroll
                for (int j = 0; j < 4; j++) o[i][j] += a[i]*b[j];
        }
    }

    // Finalize: divide by l, write ctx in [B,S,H*HD] layout
    const int b = bh / HH, h = bh % HH;
    #pragma unroll
    for (int i = 0; i < 4; i++) {
        const float inv_l = 1.0f / lrow[i];
        const int s_ = q0 + ty*4 + i;
        size_t off = ((size_t)b*SS + s_)*DD + h*HD + tx*4;
        float4 ov;
        ov.x = o[i][0]*inv_l; ov.y = o[i][1]*inv_l;
        ov.z = o[i][2]*inv_l; ov.w = o[i][3]*inv_l;
        *reinterpret_cast<float4*>(&g_ctx[off]) = ov;
    }
}

// ---------------------------------------------------------------------------
// Output projection: out = ctx[16384,768] @ Wp[768,768] + bp
// grid = (MH/64, DD/64), 256 threads, 4x4 micro.
// ---------------------------------------------------------------------------
__global__ __launch_bounds__(256) void proj_kernel(
    const float* __restrict__ Wp, const float* __restrict__ bp,
    float* __restrict__ out)
{
    const int m0 = blockIdx.x * 64;
    const int n0 = blockIdx.y * 64;

    __shared__ float As[16][68];
    __shared__ float Bs[16][64];

    const int tid = threadIdx.x;
    const int tx = tid & 15, ty = tid >> 4;
    float acc[4][4] = {};

    const int am = tid >> 2;
    const int ak = (tid & 3) * 4;
    const int bk_ = tid >> 4;
    const int bn  = (tid & 15) * 4;

    for (int kt = 0; kt < DD; kt += 16) {
        float4 av = *reinterpret_cast<const float4*>(&g_ctx[(size_t)(m0 + am) * DD + kt + ak]);
        As[ak+0][am] = av.x; As[ak+1][am] = av.y; As[ak+2][am] = av.z; As[ak+3][am] = av.w;
        float4 wv4 = *reinterpret_cast<const float4*>(&Wp[(size_t)(kt + bk_) * DD + n0 + bn]);
        *reinterpret_cast<float4*>(&Bs[bk_][bn]) = wv4;
        __syncthreads();
        #pragma unroll
        for (int kk = 0; kk < 16; kk++) {
            float a[4], b[4];
            #pragma unroll
            for (int i = 0; i < 4; i++) a[i] = As[kk][ty*4 + i];
            float4 bb = *reinterpret_cast<float4*>(&Bs[kk][tx*4]);
            b[0]=bb.x; b[1]=bb.y; b[2]=bb.z; b[3]=bb.w;
            #pragma unroll
            for (int i = 0; i < 4; i++)
                #pragma unroll
                for (int j = 0; j < 4; j++) acc[i][j] += a[i]*b[j];
        }
        __syncthreads();
    }

    float bvv[4];
    #pragma unroll
    for (int j = 0; j < 4; j++) bvv[j] = bp[n0 + tx*4 + j];
    #pragma unroll
    for (int i = 0; i < 4; i++) {
        const int m = m0 + ty*4 + i;
        size_t off = (size_t)m * DD + n0 + tx*4;
        float4 o;
        o.x = acc[i][0] + bvv[0]; o.y = acc[i][1] + bvv[1];
        o.z = acc[i][2] + bvv[2]; o.w = acc[i][3] + bvv[3];
        *reinterpret_cast<float4*>(&out[off]) = o;
    }
}

// ---------------------------------------------------------------------------
extern "C" void kernel_launch(void* const* d_in, const int* in_sizes, int n_in,
                              void* d_out, int out_size) {
    const float* x  = (const float*)d_in[0];
    const float* Wq = (const float*)d_in[1];
    const float* bq = (const float*)d_in[2];
    const float* Wk = (const float*)d_in[3];
    const float* bk = (const float*)d_in[4];
    const float* Wv = (const float*)d_in[5];
    const float* bv = (const float*)d_in[6];
    const float* Wp = (const float*)d_in[7];
    const float* bp = (const float*)d_in[8];
    float* out = (float*)d_out;

    dim3 g1(MH/64, HH, 3);
    qkv_kernel<<<g1, 256>>>(x, Wq, bq, Wk, bk, Wv, bv);

    const int attn_smem = 4 * 64 * APAD * (int)sizeof(float);   // 69632 B
    cudaFuncSetAttribute(attn_kernel, cudaFuncAttributeMaxDynamicSharedMemorySize, attn_smem);
    dim3 g2(SS/64, BB*HH);
    attn_kernel<<<g2, 256, attn_smem>>>();

    dim3 g3(MH/64, DD/64);
    proj_kernel<<<g3, 256>>>(Wp, bp, out);
}